// round 15
// baseline (speedup 1.0000x reference)
#include <cuda_runtime.h>
#include <cuda_fp16.h>

#define V_    100000
#define B_    1024
#define L_    50
#define D_    128
#define KG_   50
#define TD_   384      // 3*D
#define HID_  256      // 2*D
#define MIN_  228      // D + 2*KG

// ---------------- static device scratch ----------------
__device__ float  g_part[200 * 128];
__device__ float  g_mean[64];
__device__ float  g_invstd[64];
__device__ __half g_gxH[(size_t)B_ * L_ * TD_];    // 39.3 MB (fp16 gx)
__device__ __half g_WihH[TD_ * D_];
__device__ __half g_WhhH[TD_ * D_];
__device__ __half g_fcH[(size_t)V_ * HID_];        // 51.2 MB
__device__ float  g_mlpWT[MIN_ * HID_];
__device__ float  g_head[B_ * MIN_];
__device__ float  g_hidF[B_ * HID_];

// ---------------- helpers ----------------
__device__ __forceinline__ void mma16816(float c[4], const unsigned a[4],
                                         unsigned b0, unsigned b1) {
    asm volatile(
        "mma.sync.aligned.m16n8k16.row.col.f32.f16.f16.f32 "
        "{%0,%1,%2,%3}, {%4,%5,%6,%7}, {%8,%9}, {%0,%1,%2,%3};"
        : "+f"(c[0]), "+f"(c[1]), "+f"(c[2]), "+f"(c[3])
        : "r"(a[0]), "r"(a[1]), "r"(a[2]), "r"(a[3]), "r"(b0), "r"(b1));
}

__device__ __forceinline__ void ldsm_x4(unsigned r[4], const void* p) {
    unsigned addr = (unsigned)__cvta_generic_to_shared(p);
    asm volatile("ldmatrix.sync.aligned.m8n8.x4.shared.b16 {%0,%1,%2,%3}, [%4];"
                 : "=r"(r[0]), "=r"(r[1]), "=r"(r[2]), "=r"(r[3]) : "r"(addr));
}

__device__ __forceinline__ void cp_async16(void* smem_dst, const void* gmem_src) {
    unsigned s = (unsigned)__cvta_generic_to_shared(smem_dst);
    asm volatile("cp.async.cg.shared.global [%0], [%1], 16;" :: "r"(s), "l"(gmem_src));
}

__device__ __forceinline__ float sigm_f(float x) {
    return __fdividef(1.f, 1.f + __expf(-x));
}

__device__ __forceinline__ float tanh_ap(float x) {
    float y; asm("tanh.approx.f32 %0, %1;" : "=f"(y) : "f"(x)); return y;
}

// ---------------- Kp1: small weight conversions ----------------
__global__ void __launch_bounds__(256) k_cvt_small(const float* __restrict__ Wih,
                                                   const float* __restrict__ Whh,
                                                   const float* __restrict__ mlpW) {
    int i = blockIdx.x * 256 + threadIdx.x;
    int stride = gridDim.x * 256;
    for (int j = i; j < TD_ * D_; j += stride) {
        g_WihH[j] = __float2half_rn(Wih[j]);
        g_WhhH[j] = __float2half_rn(Whh[j]);
    }
    for (int j = i; j < HID_ * MIN_; j += stride) {
        int o = j / MIN_, k = j % MIN_;
        g_mlpWT[k * HID_ + o] = mlpW[j];
    }
}

// ---------------- K0b: finalize mean/invstd ----------------
__global__ void k_kgfin() {
    int c = threadIdx.x;
    if (c >= KG_) return;
    float S = 0.f, Q = 0.f;
    for (int i = 0; i < 200; ++i) {
        S += g_part[i * 128 + c];
        Q += g_part[i * 128 + 64 + c];
    }
    float mu  = S / (float)V_;
    float var = Q / (float)V_ - mu * mu;
    g_mean[c]   = mu;
    g_invstd[c] = rsqrtf(var + 1e-5f);
}

// ---------------- K1: GX tiles (y<3) + kgstat (y==3,x<200) + cvt_fc (y==3,x>=200) ----------------
#define GX_SMEM (2 * 128 * 136 * 2)   // 69632
__global__ void __launch_bounds__(512, 1) k_gx(const int* __restrict__ seq,
                                               const float* __restrict__ emb,
                                               const float* __restrict__ bih,
                                               const float* __restrict__ kg,
                                               const float* __restrict__ fcW) {
    extern __shared__ __half sm1[];
    int tid = threadIdx.x;

    if (blockIdx.y == 3) {
        if (blockIdx.x >= 200) {
            // ---- cvt_fc rider: 200 blocks x 512 threads ----
            size_t n = (size_t)V_ * HID_ / 4;
            size_t stride = (size_t)200 * 512;
            for (size_t j = (size_t)(blockIdx.x - 200) * 512 + tid; j < n; j += stride) {
                float4 v = ((const float4*)fcW)[j];
                ((__half2*)g_fcH)[j * 2]     = __floats2half2_rn(v.x, v.y);
                ((__half2*)g_fcH)[j * 2 + 1] = __floats2half2_rn(v.z, v.w);
            }
            return;
        }
        // ---- kgstat rider: 200 blocks, threads 0..255 ----
        __shared__ float ss[4][64], sq[4][64];
        if (tid < 256) {
            int c  = tid & 63;
            int rg = tid >> 6;
            int r0 = blockIdx.x * 500;
            float s = 0.f, q = 0.f;
            if (c < KG_) {
                for (int r = r0 + rg; r < r0 + 500; r += 4) {
                    float v = kg[(size_t)r * KG_ + c];
                    s += v; q += v * v;
                }
            }
            ss[rg][c] = s; sq[rg][c] = q;
        }
        __syncthreads();
        if (tid < 64) {
            int c = tid;
            if (c < KG_) {
                float S = ss[0][c] + ss[1][c] + ss[2][c] + ss[3][c];
                float Q = sq[0][c] + sq[1][c] + sq[2][c] + sq[3][c];
                g_part[blockIdx.x * 128 + c]      = S;
                g_part[blockIdx.x * 128 + 64 + c] = Q;
            }
        }
        return;
    }

    __half* Ah = sm1;                 // 128 x 136
    __half* Bh = sm1 + 128 * 136;     // 128 x 136
    int m0 = blockIdx.x * 128;
    int n0 = blockIdx.y * 128;

    #pragma unroll
    for (int it = 0; it < 8; ++it) {
        int lin = tid + it * 512;        // 0..4095
        int row = lin >> 5;
        int f4  = lin & 31;
        int v = seq[m0 + row];
        float4 x = *(const float4*)(emb + (size_t)v * D_ + f4 * 4);
        *(__half2*)(Ah + row * 136 + f4 * 4)     = __floats2half2_rn(x.x, x.y);
        *(__half2*)(Ah + row * 136 + f4 * 4 + 2) = __floats2half2_rn(x.z, x.w);
    }
    #pragma unroll
    for (int it = 0; it < 4; ++it) {
        int lin = tid + it * 512;        // 0..2047
        int row = lin >> 4;
        int ch  = lin & 15;
        *(uint4*)(Bh + row * 136 + ch * 8) =
            *(const uint4*)(g_WihH + (n0 + row) * D_ + ch * 8);
    }
    __syncthreads();

    int w = tid >> 5, lane = tid & 31;
    int wm = (w >> 2) * 32, wn = (w & 3) * 32;
    int r = lane >> 2, q = (lane & 3) * 2;

    float c[2][4][4];
    #pragma unroll
    for (int i = 0; i < 2; ++i)
        #pragma unroll
        for (int j = 0; j < 4; ++j)
            #pragma unroll
            for (int t = 0; t < 4; ++t) c[i][j][t] = 0.f;

    #pragma unroll
    for (int ks = 0; ks < 8; ++ks) {
        int k0 = ks * 16;
        unsigned a[2][4];
        #pragma unroll
        for (int i = 0; i < 2; ++i) {
            const __half* p = Ah + (wm + i * 16) * 136 + k0;
            a[i][0] = *(const unsigned*)(p + r * 136 + q);
            a[i][1] = *(const unsigned*)(p + (r + 8) * 136 + q);
            a[i][2] = *(const unsigned*)(p + r * 136 + 8 + q);
            a[i][3] = *(const unsigned*)(p + (r + 8) * 136 + 8 + q);
        }
        #pragma unroll
        for (int j = 0; j < 4; ++j) {
            const __half* pb = Bh + (wn + j * 8 + r) * 136 + k0;
            unsigned b0 = *(const unsigned*)(pb + q);
            unsigned b1 = *(const unsigned*)(pb + 8 + q);
            mma16816(c[0][j], a[0], b0, b1);
            mma16816(c[1][j], a[1], b0, b1);
        }
    }
    #pragma unroll
    for (int i = 0; i < 2; ++i) {
        int row = m0 + wm + i * 16 + r;
        #pragma unroll
        for (int j = 0; j < 4; ++j) {
            int col = n0 + wn + j * 8 + q;
            float b0 = __ldg(bih + col), b1 = __ldg(bih + col + 1);
            *(__half2*)(g_gxH + (size_t)row * TD_ + col) =
                __floats2half2_rn(c[i][j][0] + b0, c[i][j][1] + b1);
            *(__half2*)(g_gxH + (size_t)(row + 8) * TD_ + col) =
                __floats2half2_rn(c[i][j][2] + b0, c[i][j][3] + b1);
        }
    }
}

// ---------------- K2: fused gru (b<128) + bkg (128..383) ----------------
#define GRU_SMEM 32416
#define GRU_GRID 384
__global__ void __launch_bounds__(256, 1) k_gru(const int* __restrict__ tlen,
                                                const float* __restrict__ bhh,
                                                const int* __restrict__ seq,
                                                const float* __restrict__ kg,
                                                const float* __restrict__ mlphW,
                                                const float* __restrict__ mlphb) {
    int tid = threadIdx.x;
    int bid = blockIdx.x;

    if (bid >= 128) {
        // ---- bkg rider: 256 blocks x 4 batch rows ----
        __shared__ int   sseq[4][L_ + 2];
        __shared__ float sbkg[4][64];
        int sub = tid >> 6;          // 0..3
        int c   = tid & 63;
        int b   = (bid - 128) * 4 + sub;
        if (c < L_) sseq[sub][c] = seq[b * L_ + c];
        __syncthreads();
        if (c < KG_) {
            float acc = 0.f;
            #pragma unroll 10
            for (int t = 0; t < L_; ++t) acc += kg[(size_t)sseq[sub][t] * KG_ + c];
            float val = (acc - (float)L_ * g_mean[c]) * g_invstd[c] / (float)tlen[b];
            sbkg[sub][c] = val;
            g_head[b * MIN_ + D_ + c] = val;
        }
        __syncthreads();
        if (c < KG_) {
            float acc = mlphb[c];
            #pragma unroll 10
            for (int k = 0; k < KG_; ++k) acc += sbkg[sub][k] * mlphW[c * KG_ + k];
            g_head[b * MIN_ + D_ + KG_ + c] = acc;
        }
        return;
    }

    // ---- GRU: register-resident Whh, 2 syncs/step ----
    extern __shared__ char smraw[];
    __half* sH16 = (__half*)smraw;                 // 8 x 136
    __half* sGx  = sH16 + 1088;                    // 2 x 3072 halves
    float*  sGh  = (float*)(sGx + 6144);           // 384 x 9 (gh^T)
    float*  sHf  = sGh + 3456;                     // 8 x 128
    int*    slen = (int*)(sHf + 1024);             // 8

    int rbase = bid * 8;
    int lane = tid & 31, w = tid >> 5;
    int r = lane >> 2, q2 = (lane & 3) * 2;

    unsigned aW[8][3][4];
    #pragma unroll
    for (int ks = 0; ks < 8; ++ks) {
        int k0 = ks * 16;
        #pragma unroll
        for (int mt = 0; mt < 3; ++mt) {
            int R = w * 48 + mt * 16;
            aW[ks][mt][0] = *(const unsigned*)(g_WhhH + (R + r) * D_ + k0 + q2);
            aW[ks][mt][1] = *(const unsigned*)(g_WhhH + (R + 8 + r) * D_ + k0 + q2);
            aW[ks][mt][2] = *(const unsigned*)(g_WhhH + (R + r) * D_ + k0 + 8 + q2);
            aW[ks][mt][3] = *(const unsigned*)(g_WhhH + (R + 8 + r) * D_ + k0 + 8 + q2);
        }
    }

    int dd = tid & 127;
    float bhr = bhh[dd], bhz = bhh[128 + dd], bhn = bhh[256 + dd];

    for (int j = tid; j < 1024; j += 256) sHf[j] = 0.f;
    for (int j = tid; j < 1088; j += 256) sH16[j] = __float2half_rn(0.f);
    if (tid < 8) slen[tid] = tlen[rbase + tid];

    #pragma unroll
    for (int j = 0; j < 2; ++j) {
        int e = tid + j * 256;
        if (e < 384) {
            int rr = e / 48, qq = e % 48;
            cp_async16(sGx + rr * 384 + qq * 8,
                       g_gxH + ((size_t)(rbase + rr) * L_) * TD_ + qq * 8);
        }
    }
    asm volatile("cp.async.commit_group;");
    __syncthreads();

    int maxlen = 0;
    #pragma unroll
    for (int i = 0; i < 8; ++i) maxlen = max(maxlen, slen[i]);

    for (int t = 0; t < maxlen; ++t) {
        int buf = t & 1;
        if (t + 1 < maxlen) {
            #pragma unroll
            for (int j = 0; j < 2; ++j) {
                int e = tid + j * 256;
                if (e < 384) {
                    int rr = e / 48, qq = e % 48;
                    cp_async16(sGx + (buf ^ 1) * 3072 + rr * 384 + qq * 8,
                               g_gxH + ((size_t)(rbase + rr) * L_ + (t + 1)) * TD_ + qq * 8);
                }
            }
        }
        asm volatile("cp.async.commit_group;");

        {
            float c[3][4];
            #pragma unroll
            for (int mt = 0; mt < 3; ++mt)
                c[mt][0] = c[mt][1] = c[mt][2] = c[mt][3] = 0.f;
            #pragma unroll
            for (int ks = 0; ks < 8; ++ks) {
                int k0 = ks * 16;
                unsigned b0 = *(const unsigned*)(sH16 + r * 136 + k0 + q2);
                unsigned b1 = *(const unsigned*)(sH16 + r * 136 + k0 + 8 + q2);
                #pragma unroll
                for (int mt = 0; mt < 3; ++mt)
                    mma16816(c[mt], aW[ks][mt], b0, b1);
            }
            #pragma unroll
            for (int mt = 0; mt < 3; ++mt) {
                int R = w * 48 + mt * 16;
                int col = (lane & 3) * 2;
                sGh[(R + r) * 9 + col]         = c[mt][0];
                sGh[(R + r) * 9 + col + 1]     = c[mt][1];
                sGh[(R + 8 + r) * 9 + col]     = c[mt][2];
                sGh[(R + 8 + r) * 9 + col + 1] = c[mt][3];
            }
        }
        asm volatile("cp.async.wait_group 1;");
        __syncthreads();

        #pragma unroll
        for (int j = 0; j < 4; ++j) {
            int e = tid + j * 256;
            int rr = e >> 7;
            if (t < slen[rr]) {
                const __half* gx = sGx + buf * 3072 + rr * 384;
                float ghr = sGh[dd * 9 + rr]         + bhr;
                float ghz = sGh[(128 + dd) * 9 + rr] + bhz;
                float ghn = sGh[(256 + dd) * 9 + rr] + bhn;
                float xr = __half2float(gx[dd])       + ghr;
                float xz = __half2float(gx[128 + dd]) + ghz;
                float rg = fmaf(0.5f, tanh_ap(0.5f * xr), 0.5f);
                float z  = fmaf(0.5f, tanh_ap(0.5f * xz), 0.5f);
                float nn = 2.f * sigm_f(2.f * (__half2float(gx[256 + dd]) + rg * ghn)) - 1.f;
                float h  = sHf[rr * 128 + dd];
                float hn = (1.f - z) * nn + z * h;
                sHf[rr * 128 + dd] = hn;
                sH16[rr * 136 + dd] = __float2half_rn(hn);
            }
        }
        __syncthreads();
    }
    asm volatile("cp.async.wait_all;");

    #pragma unroll
    for (int j = 0; j < 4; ++j) {
        int e = tid + j * 256;
        int rr = e >> 7;
        g_head[(rbase + rr) * MIN_ + dd] = sHf[rr * 128 + dd];
    }
}

// ---------------- K4: hidden = tanh(g_head @ mlp_W^T + mlp_b) -> fp32 ----------------
__global__ void __launch_bounds__(256) k_mlp(const float* __restrict__ mlpb) {
    __shared__ float sIn[16 * MIN_];
    int tid = threadIdx.x;
    int rbase = blockIdx.x * 16;
    for (int j = tid; j < 16 * MIN_; j += 256) {
        int rr = j / MIN_, kk = j % MIN_;
        sIn[j] = g_head[(rbase + rr) * MIN_ + kk];
    }
    __syncthreads();
    int o = tid;
    float acc[16];
    float bb = mlpb[o];
    #pragma unroll
    for (int i = 0; i < 16; ++i) acc[i] = bb;
    for (int k = 0; k < MIN_; ++k) {
        float wv = g_mlpWT[k * HID_ + o];
        #pragma unroll
        for (int i = 0; i < 16; ++i) acc[i] += sIn[i * MIN_ + k] * wv;
    }
    #pragma unroll
    for (int i = 0; i < 16; ++i)
        g_hidF[(size_t)(rbase + i) * HID_ + o] = tanhf(acc[i]);
}

// ---------------- K5: out = hidden @ fc_W^T + fc_b ----------------
// M-tile 128, grid (37,8) = 296 CTAs, 2 CTAs/SM (32 warps/SM resident).
// A: 128x264 resident (67.6KB). B: K-chunks of 64 halves, 2 x (128x72) bufs
// (36.9KB). Total smem 104.4KB -> 2 CTAs/SM. 512 thr, warp tile 32x32.
#define NTILES 782
#define FC_SMEM (128 * 264 * 2 + 2 * 128 * 72 * 2)   // 104448
__global__ void __launch_bounds__(512, 2) k_fc(const float* __restrict__ fcb,
                                               float* __restrict__ out) {
    extern __shared__ __half sm5[];
    __half* Ah = sm5;                   // 128 x 264 (full K=256)
    __half* Bb = sm5 + 128 * 264;       // 2 x (128 x 72)
    int tid = threadIdx.x;
    int m0 = blockIdx.y * 128;

    #pragma unroll
    for (int it = 0; it < 16; ++it) {
        int lin = tid + it * 512;        // 0..8191 float4 units
        int row = lin >> 6;
        int c4  = lin & 63;
        float4 v = *(const float4*)(g_hidF + (size_t)(m0 + row) * HID_ + c4 * 4);
        *(__half2*)(Ah + row * 264 + c4 * 4)     = __floats2half2_rn(v.x, v.y);
        *(__half2*)(Ah + row * 264 + c4 * 4 + 2) = __floats2half2_rn(v.z, v.w);
    }

    int w = tid >> 5, lane = tid & 31;
    int wm = (w >> 2) * 32, wn = (w & 3) * 32;
    int r = lane >> 2, q = (lane & 3) * 2;

    int aoff = (lane & 15) * 264 + (lane >> 4) * 8;   // A ldsm: 16 rows x 16 K
    int boff = (lane & 15) * 72 + (lane >> 4) * 8;    // B ldsm: 16 rows x 16 K

    // load one K-chunk (64 halves) of tile nt into buffer buf
    auto loadChunk = [&](int nt, int kc, int buf) {
        int n0 = nt * 128;
        __half* dst = Bb + buf * 128 * 72;
        #pragma unroll
        for (int it = 0; it < 2; ++it) {
            int lin = tid + it * 512;    // 0..1023 (128 rows x 8 chunks)
            int row = lin >> 3;
            int ch  = lin & 7;
            if (n0 + row < V_)
                cp_async16(dst + row * 72 + ch * 8,
                           g_fcH + (size_t)(n0 + row) * HID_ + kc * 64 + ch * 8);
            else
                *(uint4*)(dst + row * 72 + ch * 8) = make_uint4(0u, 0u, 0u, 0u);
        }
        asm volatile("cp.async.commit_group;");
    };

    int grid = gridDim.x;
    int nt = blockIdx.x;
    loadChunk(nt, 0, 0);
    int buf = 0;

    for (; nt < NTILES; nt += grid) {
        float c[2][4][4];
        #pragma unroll
        for (int mi = 0; mi < 2; ++mi)
            #pragma unroll
            for (int j = 0; j < 4; ++j)
                #pragma unroll
                for (int t = 0; t < 4; ++t) c[mi][j][t] = 0.f;

        #pragma unroll
        for (int kc = 0; kc < 4; ++kc) {
            int nnt = (kc < 3) ? nt : nt + grid;
            int nkc = (kc + 1) & 3;
            __syncthreads();                       // prior compute on buf^1 done
            if (nnt < NTILES) {
                loadChunk(nnt, nkc, buf ^ 1);
                asm volatile("cp.async.wait_group 1;");
            } else {
                asm volatile("cp.async.wait_group 0;");
            }
            __syncthreads();                       // current buf visible

            const __half* B0 = Bb + buf * 128 * 72;
            #pragma unroll
            for (int ks = 0; ks < 4; ++ks) {
                int k0 = ks * 16;                  // within-chunk (<=48)
                int ka = kc * 64 + k0;             // A K offset
                unsigned a[2][4];
                #pragma unroll
                for (int mi = 0; mi < 2; ++mi)
                    ldsm_x4(a[mi], Ah + (wm + mi * 16) * 264 + ka + aoff);
                #pragma unroll
                for (int jp = 0; jp < 2; ++jp) {
                    unsigned bf[4];
                    ldsm_x4(bf, B0 + (wn + jp * 16) * 72 + k0 + boff);
                    #pragma unroll
                    for (int mi = 0; mi < 2; ++mi) {
                        mma16816(c[mi][2 * jp],     a[mi], bf[0], bf[2]);
                        mma16816(c[mi][2 * jp + 1], a[mi], bf[1], bf[3]);
                    }
                }
            }
            buf ^= 1;
        }

        int n0 = nt * 128;
        #pragma unroll
        for (int mi = 0; mi < 2; ++mi) {
            int row = m0 + wm + mi * 16 + r;
            #pragma unroll
            for (int j = 0; j < 4; ++j) {
                int col = n0 + wn + j * 8 + q;
                if (col < V_) {
                    float2 bv = *(const float2*)(fcb + col);
                    *(float2*)(out + (size_t)row * V_ + col) =
                        make_float2(c[mi][j][0] + bv.x, c[mi][j][1] + bv.y);
                    *(float2*)(out + (size_t)(row + 8) * V_ + col) =
                        make_float2(c[mi][j][2] + bv.x, c[mi][j][3] + bv.y);
                }
            }
        }
    }
}

// ---------------- launch (single stream; overlap via fused heterogeneous grids) ----------------
extern "C" void kernel_launch(void* const* d_in, const int* in_sizes, int n_in,
                              void* d_out, int out_size) {
    const int*   seq   = (const int*)d_in[0];
    const int*   tlen  = (const int*)d_in[1];
    const float* emb   = (const float*)d_in[2];
    const float* kg    = (const float*)d_in[3];
    const float* Wih   = (const float*)d_in[4];
    const float* Whh   = (const float*)d_in[5];
    const float* bih   = (const float*)d_in[6];
    const float* bhh   = (const float*)d_in[7];
    const float* mlphW = (const float*)d_in[8];
    const float* mlphb = (const float*)d_in[9];
    const float* mlpW  = (const float*)d_in[10];
    const float* mlpb  = (const float*)d_in[11];
    const float* fcW   = (const float*)d_in[12];
    const float* fcb   = (const float*)d_in[13];
    float* out = (float*)d_out;

    cudaFuncSetAttribute(k_gx,  cudaFuncAttributeMaxDynamicSharedMemorySize, GX_SMEM);
    cudaFuncSetAttribute(k_gru, cudaFuncAttributeMaxDynamicSharedMemorySize, GRU_SMEM);
    cudaFuncSetAttribute(k_fc,  cudaFuncAttributeMaxDynamicSharedMemorySize, FC_SMEM);

    k_cvt_small<<<48, 256>>>(Wih, Whh, mlpW);
    k_gx<<<dim3(400, 4), 512, GX_SMEM>>>(seq, emb, bih, kg, fcW);  // gx + kgstat + cvt_fc
    k_kgfin<<<1, 64>>>();
    k_gru<<<GRU_GRID, 256, GRU_SMEM>>>(tlen, bhh, seq, kg, mlphW, mlphb);  // gru + bkg
    k_mlp<<<64, 256>>>(mlpb);
    k_fc<<<dim3(37, 8), 512, FC_SMEM>>>(fcb, out);
}

// round 16
// speedup vs baseline: 1.0626x; 1.0626x over previous
#include <cuda_runtime.h>
#include <cuda_fp16.h>

#define V_    100000
#define B_    1024
#define L_    50
#define D_    128
#define KG_   50
#define TD_   384      // 3*D
#define HID_  256      // 2*D
#define MIN_  228      // D + 2*KG

// ---------------- static device scratch ----------------
__device__ float  g_part[200 * 128];
__device__ float  g_mean[64];
__device__ float  g_invstd[64];
__device__ __half g_gxH[(size_t)B_ * L_ * TD_];    // 39.3 MB (fp16 gx)
__device__ __half g_WihH[TD_ * D_];
__device__ __half g_WhhH[TD_ * D_];
__device__ __half g_fcH[(size_t)V_ * HID_];        // 51.2 MB
__device__ float  g_mlpWT[MIN_ * HID_];
__device__ float  g_head[B_ * MIN_];
__device__ float  g_hidF[B_ * HID_];

// ---------------- helpers ----------------
__device__ __forceinline__ void mma16816(float c[4], const unsigned a[4],
                                         unsigned b0, unsigned b1) {
    asm volatile(
        "mma.sync.aligned.m16n8k16.row.col.f32.f16.f16.f32 "
        "{%0,%1,%2,%3}, {%4,%5,%6,%7}, {%8,%9}, {%0,%1,%2,%3};"
        : "+f"(c[0]), "+f"(c[1]), "+f"(c[2]), "+f"(c[3])
        : "r"(a[0]), "r"(a[1]), "r"(a[2]), "r"(a[3]), "r"(b0), "r"(b1));
}

__device__ __forceinline__ void ldsm_x4(unsigned r[4], const void* p) {
    unsigned addr = (unsigned)__cvta_generic_to_shared(p);
    asm volatile("ldmatrix.sync.aligned.m8n8.x4.shared.b16 {%0,%1,%2,%3}, [%4];"
                 : "=r"(r[0]), "=r"(r[1]), "=r"(r[2]), "=r"(r[3]) : "r"(addr));
}

__device__ __forceinline__ void cp_async16(void* smem_dst, const void* gmem_src) {
    unsigned s = (unsigned)__cvta_generic_to_shared(smem_dst);
    asm volatile("cp.async.cg.shared.global [%0], [%1], 16;" :: "r"(s), "l"(gmem_src));
}

__device__ __forceinline__ float sigm_f(float x) {
    return __fdividef(1.f, 1.f + __expf(-x));
}

__device__ __forceinline__ float tanh_ap(float x) {
    float y; asm("tanh.approx.f32 %0, %1;" : "=f"(y) : "f"(x)); return y;
}

// ---------------- Kp1: small weight conversions ----------------
__global__ void __launch_bounds__(256) k_cvt_small(const float* __restrict__ Wih,
                                                   const float* __restrict__ Whh,
                                                   const float* __restrict__ mlpW) {
    int i = blockIdx.x * 256 + threadIdx.x;
    int stride = gridDim.x * 256;
    for (int j = i; j < TD_ * D_; j += stride) {
        g_WihH[j] = __float2half_rn(Wih[j]);
        g_WhhH[j] = __float2half_rn(Whh[j]);
    }
    for (int j = i; j < HID_ * MIN_; j += stride) {
        int o = j / MIN_, k = j % MIN_;
        g_mlpWT[k * HID_ + o] = mlpW[j];
    }
}

// ---------------- K0b: finalize mean/invstd ----------------
__global__ void k_kgfin() {
    int c = threadIdx.x;
    if (c >= KG_) return;
    float S = 0.f, Q = 0.f;
    for (int i = 0; i < 200; ++i) {
        S += g_part[i * 128 + c];
        Q += g_part[i * 128 + 64 + c];
    }
    float mu  = S / (float)V_;
    float var = Q / (float)V_ - mu * mu;
    g_mean[c]   = mu;
    g_invstd[c] = rsqrtf(var + 1e-5f);
}

// ---------------- K1: GX tiles (y<3) + kgstat (y==3,x<200) + cvt_fc (y==3,x>=200) ----------------
#define GX_SMEM (2 * 128 * 136 * 2)   // 69632
__global__ void __launch_bounds__(512, 1) k_gx(const int* __restrict__ seq,
                                               const float* __restrict__ emb,
                                               const float* __restrict__ bih,
                                               const float* __restrict__ kg,
                                               const float* __restrict__ fcW) {
    extern __shared__ __half sm1[];
    int tid = threadIdx.x;

    if (blockIdx.y == 3) {
        if (blockIdx.x >= 200) {
            // ---- cvt_fc rider: 200 blocks x 512 threads ----
            size_t n = (size_t)V_ * HID_ / 4;
            size_t stride = (size_t)200 * 512;
            for (size_t j = (size_t)(blockIdx.x - 200) * 512 + tid; j < n; j += stride) {
                float4 v = ((const float4*)fcW)[j];
                ((__half2*)g_fcH)[j * 2]     = __floats2half2_rn(v.x, v.y);
                ((__half2*)g_fcH)[j * 2 + 1] = __floats2half2_rn(v.z, v.w);
            }
            return;
        }
        // ---- kgstat rider: 200 blocks, threads 0..255 ----
        __shared__ float ss[4][64], sq[4][64];
        if (tid < 256) {
            int c  = tid & 63;
            int rg = tid >> 6;
            int r0 = blockIdx.x * 500;
            float s = 0.f, q = 0.f;
            if (c < KG_) {
                for (int r = r0 + rg; r < r0 + 500; r += 4) {
                    float v = kg[(size_t)r * KG_ + c];
                    s += v; q += v * v;
                }
            }
            ss[rg][c] = s; sq[rg][c] = q;
        }
        __syncthreads();
        if (tid < 64) {
            int c = tid;
            if (c < KG_) {
                float S = ss[0][c] + ss[1][c] + ss[2][c] + ss[3][c];
                float Q = sq[0][c] + sq[1][c] + sq[2][c] + sq[3][c];
                g_part[blockIdx.x * 128 + c]      = S;
                g_part[blockIdx.x * 128 + 64 + c] = Q;
            }
        }
        return;
    }

    __half* Ah = sm1;                 // 128 x 136
    __half* Bh = sm1 + 128 * 136;     // 128 x 136
    int m0 = blockIdx.x * 128;
    int n0 = blockIdx.y * 128;

    #pragma unroll
    for (int it = 0; it < 8; ++it) {
        int lin = tid + it * 512;        // 0..4095
        int row = lin >> 5;
        int f4  = lin & 31;
        int v = seq[m0 + row];
        float4 x = *(const float4*)(emb + (size_t)v * D_ + f4 * 4);
        *(__half2*)(Ah + row * 136 + f4 * 4)     = __floats2half2_rn(x.x, x.y);
        *(__half2*)(Ah + row * 136 + f4 * 4 + 2) = __floats2half2_rn(x.z, x.w);
    }
    #pragma unroll
    for (int it = 0; it < 4; ++it) {
        int lin = tid + it * 512;        // 0..2047
        int row = lin >> 4;
        int ch  = lin & 15;
        *(uint4*)(Bh + row * 136 + ch * 8) =
            *(const uint4*)(g_WihH + (n0 + row) * D_ + ch * 8);
    }
    __syncthreads();

    int w = tid >> 5, lane = tid & 31;
    int wm = (w >> 2) * 32, wn = (w & 3) * 32;
    int r = lane >> 2, q = (lane & 3) * 2;

    float c[2][4][4];
    #pragma unroll
    for (int i = 0; i < 2; ++i)
        #pragma unroll
        for (int j = 0; j < 4; ++j)
            #pragma unroll
            for (int t = 0; t < 4; ++t) c[i][j][t] = 0.f;

    #pragma unroll
    for (int ks = 0; ks < 8; ++ks) {
        int k0 = ks * 16;
        unsigned a[2][4];
        #pragma unroll
        for (int i = 0; i < 2; ++i) {
            const __half* p = Ah + (wm + i * 16) * 136 + k0;
            a[i][0] = *(const unsigned*)(p + r * 136 + q);
            a[i][1] = *(const unsigned*)(p + (r + 8) * 136 + q);
            a[i][2] = *(const unsigned*)(p + r * 136 + 8 + q);
            a[i][3] = *(const unsigned*)(p + (r + 8) * 136 + 8 + q);
        }
        #pragma unroll
        for (int j = 0; j < 4; ++j) {
            const __half* pb = Bh + (wn + j * 8 + r) * 136 + k0;
            unsigned b0 = *(const unsigned*)(pb + q);
            unsigned b1 = *(const unsigned*)(pb + 8 + q);
            mma16816(c[0][j], a[0], b0, b1);
            mma16816(c[1][j], a[1], b0, b1);
        }
    }
    #pragma unroll
    for (int i = 0; i < 2; ++i) {
        int row = m0 + wm + i * 16 + r;
        #pragma unroll
        for (int j = 0; j < 4; ++j) {
            int col = n0 + wn + j * 8 + q;
            float b0 = __ldg(bih + col), b1 = __ldg(bih + col + 1);
            *(__half2*)(g_gxH + (size_t)row * TD_ + col) =
                __floats2half2_rn(c[i][j][0] + b0, c[i][j][1] + b1);
            *(__half2*)(g_gxH + (size_t)(row + 8) * TD_ + col) =
                __floats2half2_rn(c[i][j][2] + b0, c[i][j][3] + b1);
        }
    }
}

// ---------------- K2: fused gru (b<128) + bkg (128..383) ----------------
#define GRU_SMEM 32416
#define GRU_GRID 384
__global__ void __launch_bounds__(256, 1) k_gru(const int* __restrict__ tlen,
                                                const float* __restrict__ bhh,
                                                const int* __restrict__ seq,
                                                const float* __restrict__ kg,
                                                const float* __restrict__ mlphW,
                                                const float* __restrict__ mlphb) {
    int tid = threadIdx.x;
    int bid = blockIdx.x;

    if (bid >= 128) {
        // ---- bkg rider: 256 blocks x 4 batch rows ----
        __shared__ int   sseq[4][L_ + 2];
        __shared__ float sbkg[4][64];
        int sub = tid >> 6;          // 0..3
        int c   = tid & 63;
        int b   = (bid - 128) * 4 + sub;
        if (c < L_) sseq[sub][c] = seq[b * L_ + c];
        __syncthreads();
        if (c < KG_) {
            float acc = 0.f;
            #pragma unroll 10
            for (int t = 0; t < L_; ++t) acc += kg[(size_t)sseq[sub][t] * KG_ + c];
            float val = (acc - (float)L_ * g_mean[c]) * g_invstd[c] / (float)tlen[b];
            sbkg[sub][c] = val;
            g_head[b * MIN_ + D_ + c] = val;
        }
        __syncthreads();
        if (c < KG_) {
            float acc = mlphb[c];
            #pragma unroll 10
            for (int k = 0; k < KG_; ++k) acc += sbkg[sub][k] * mlphW[c * KG_ + k];
            g_head[b * MIN_ + D_ + KG_ + c] = acc;
        }
        return;
    }

    // ---- GRU: register-resident Whh, 2 syncs/step ----
    extern __shared__ char smraw[];
    __half* sH16 = (__half*)smraw;                 // 8 x 136
    __half* sGx  = sH16 + 1088;                    // 2 x 3072 halves
    float*  sGh  = (float*)(sGx + 6144);           // 384 x 9 (gh^T)
    float*  sHf  = sGh + 3456;                     // 8 x 128
    int*    slen = (int*)(sHf + 1024);             // 8

    int rbase = bid * 8;
    int lane = tid & 31, w = tid >> 5;
    int r = lane >> 2, q2 = (lane & 3) * 2;

    unsigned aW[8][3][4];
    #pragma unroll
    for (int ks = 0; ks < 8; ++ks) {
        int k0 = ks * 16;
        #pragma unroll
        for (int mt = 0; mt < 3; ++mt) {
            int R = w * 48 + mt * 16;
            aW[ks][mt][0] = *(const unsigned*)(g_WhhH + (R + r) * D_ + k0 + q2);
            aW[ks][mt][1] = *(const unsigned*)(g_WhhH + (R + 8 + r) * D_ + k0 + q2);
            aW[ks][mt][2] = *(const unsigned*)(g_WhhH + (R + r) * D_ + k0 + 8 + q2);
            aW[ks][mt][3] = *(const unsigned*)(g_WhhH + (R + 8 + r) * D_ + k0 + 8 + q2);
        }
    }

    int dd = tid & 127;
    float bhr = bhh[dd], bhz = bhh[128 + dd], bhn = bhh[256 + dd];

    for (int j = tid; j < 1024; j += 256) sHf[j] = 0.f;
    for (int j = tid; j < 1088; j += 256) sH16[j] = __float2half_rn(0.f);
    if (tid < 8) slen[tid] = tlen[rbase + tid];

    #pragma unroll
    for (int j = 0; j < 2; ++j) {
        int e = tid + j * 256;
        if (e < 384) {
            int rr = e / 48, qq = e % 48;
            cp_async16(sGx + rr * 384 + qq * 8,
                       g_gxH + ((size_t)(rbase + rr) * L_) * TD_ + qq * 8);
        }
    }
    asm volatile("cp.async.commit_group;");
    __syncthreads();

    int maxlen = 0;
    #pragma unroll
    for (int i = 0; i < 8; ++i) maxlen = max(maxlen, slen[i]);

    for (int t = 0; t < maxlen; ++t) {
        int buf = t & 1;
        if (t + 1 < maxlen) {
            #pragma unroll
            for (int j = 0; j < 2; ++j) {
                int e = tid + j * 256;
                if (e < 384) {
                    int rr = e / 48, qq = e % 48;
                    cp_async16(sGx + (buf ^ 1) * 3072 + rr * 384 + qq * 8,
                               g_gxH + ((size_t)(rbase + rr) * L_ + (t + 1)) * TD_ + qq * 8);
                }
            }
        }
        asm volatile("cp.async.commit_group;");

        {
            float c[3][4];
            #pragma unroll
            for (int mt = 0; mt < 3; ++mt)
                c[mt][0] = c[mt][1] = c[mt][2] = c[mt][3] = 0.f;
            #pragma unroll
            for (int ks = 0; ks < 8; ++ks) {
                int k0 = ks * 16;
                unsigned b0 = *(const unsigned*)(sH16 + r * 136 + k0 + q2);
                unsigned b1 = *(const unsigned*)(sH16 + r * 136 + k0 + 8 + q2);
                #pragma unroll
                for (int mt = 0; mt < 3; ++mt)
                    mma16816(c[mt], aW[ks][mt], b0, b1);
            }
            #pragma unroll
            for (int mt = 0; mt < 3; ++mt) {
                int R = w * 48 + mt * 16;
                int col = (lane & 3) * 2;
                sGh[(R + r) * 9 + col]         = c[mt][0];
                sGh[(R + r) * 9 + col + 1]     = c[mt][1];
                sGh[(R + 8 + r) * 9 + col]     = c[mt][2];
                sGh[(R + 8 + r) * 9 + col + 1] = c[mt][3];
            }
        }
        asm volatile("cp.async.wait_group 1;");
        __syncthreads();

        #pragma unroll
        for (int j = 0; j < 4; ++j) {
            int e = tid + j * 256;
            int rr = e >> 7;
            if (t < slen[rr]) {
                const __half* gx = sGx + buf * 3072 + rr * 384;
                float ghr = sGh[dd * 9 + rr]         + bhr;
                float ghz = sGh[(128 + dd) * 9 + rr] + bhz;
                float ghn = sGh[(256 + dd) * 9 + rr] + bhn;
                float xr = __half2float(gx[dd])       + ghr;
                float xz = __half2float(gx[128 + dd]) + ghz;
                float rg = fmaf(0.5f, tanh_ap(0.5f * xr), 0.5f);
                float z  = fmaf(0.5f, tanh_ap(0.5f * xz), 0.5f);
                float nn = 2.f * sigm_f(2.f * (__half2float(gx[256 + dd]) + rg * ghn)) - 1.f;
                float h  = sHf[rr * 128 + dd];
                float hn = (1.f - z) * nn + z * h;
                sHf[rr * 128 + dd] = hn;
                sH16[rr * 136 + dd] = __float2half_rn(hn);
            }
        }
        __syncthreads();
    }
    asm volatile("cp.async.wait_all;");

    #pragma unroll
    for (int j = 0; j < 4; ++j) {
        int e = tid + j * 256;
        int rr = e >> 7;
        g_head[(rbase + rr) * MIN_ + dd] = sHf[rr * 128 + dd];
    }
}

// ---------------- K4: hidden = tanh(g_head @ mlp_W^T + mlp_b) -> fp32 ----------------
__global__ void __launch_bounds__(256) k_mlp(const float* __restrict__ mlpb) {
    __shared__ float sIn[16 * MIN_];
    int tid = threadIdx.x;
    int rbase = blockIdx.x * 16;
    for (int j = tid; j < 16 * MIN_; j += 256) {
        int rr = j / MIN_, kk = j % MIN_;
        sIn[j] = g_head[(rbase + rr) * MIN_ + kk];
    }
    __syncthreads();
    int o = tid;
    float acc[16];
    float bb = mlpb[o];
    #pragma unroll
    for (int i = 0; i < 16; ++i) acc[i] = bb;
    for (int k = 0; k < MIN_; ++k) {
        float wv = g_mlpWT[k * HID_ + o];
        #pragma unroll
        for (int i = 0; i < 16; ++i) acc[i] += sIn[i * MIN_ + k] * wv;
    }
    #pragma unroll
    for (int i = 0; i < 16; ++i)
        g_hidF[(size_t)(rbase + i) * HID_ + o] = tanhf(acc[i]);
}

// ---------------- K5: out = hidden @ fc_W^T + fc_b  (R13-best: M256, grid(37,4)) ----------------
// A: 256x264 halves resident. B: 2 x (128x136) K-chunk buffers, cp.async pipelined.
// ldmatrix.x4 for A and B fragments. 148 CTAs = 1 full wave, B ~L2-resident.
#define NTILES 782
#define FC_SMEM (256 * 264 * 2 + 2 * 128 * 136 * 2)   // 204800
__global__ void __launch_bounds__(512, 1) k_fc(const float* __restrict__ fcb,
                                               float* __restrict__ out) {
    extern __shared__ __half sm5[];
    __half* Ah = sm5;                   // 256 x 264 (full K=256)
    __half* Bb = sm5 + 256 * 264;       // 2 x (128 x 136)
    int tid = threadIdx.x;
    int m0 = blockIdx.y * 256;

    #pragma unroll
    for (int it = 0; it < 32; ++it) {
        int lin = tid + it * 512;        // 0..16383 float4 units
        int row = lin >> 6;
        int c4  = lin & 63;
        float4 v = *(const float4*)(g_hidF + (size_t)(m0 + row) * HID_ + c4 * 4);
        *(__half2*)(Ah + row * 264 + c4 * 4)     = __floats2half2_rn(v.x, v.y);
        *(__half2*)(Ah + row * 264 + c4 * 4 + 2) = __floats2half2_rn(v.z, v.w);
    }

    int w = tid >> 5, lane = tid & 31;
    int wm = (w >> 2) * 64, wn = (w & 3) * 32;
    int r = lane >> 2, q = (lane & 3) * 2;

    int aoff = (lane & 15) * 264 + (lane >> 4) * 8;
    int boff = (lane & 15) * 136 + (lane >> 4) * 8;

    auto loadChunk = [&](int nt, int kc, int buf) {
        int n0 = nt * 128;
        __half* dst = Bb + buf * 128 * 136;
        #pragma unroll
        for (int it = 0; it < 4; ++it) {
            int lin = tid + it * 512;    // 0..2047 (128 rows x 16 chunks)
            int row = lin >> 4;
            int ch  = lin & 15;
            if (n0 + row < V_)
                cp_async16(dst + row * 136 + ch * 8,
                           g_fcH + (size_t)(n0 + row) * HID_ + kc * 128 + ch * 8);
            else
                *(uint4*)(dst + row * 136 + ch * 8) = make_uint4(0u, 0u, 0u, 0u);
        }
        asm volatile("cp.async.commit_group;");
    };

    int grid = gridDim.x;
    int nt = blockIdx.x;
    loadChunk(nt, 0, 0);
    int buf = 0;

    for (; nt < NTILES; nt += grid) {
        float c[4][4][4];
        #pragma unroll
        for (int mi = 0; mi < 4; ++mi)
            #pragma unroll
            for (int j = 0; j < 4; ++j)
                #pragma unroll
                for (int t = 0; t < 4; ++t) c[mi][j][t] = 0.f;

        #pragma unroll
        for (int kc = 0; kc < 2; ++kc) {
            int nnt = (kc == 0) ? nt : nt + grid;
            int nkc = kc ^ 1;
            __syncthreads();
            if (nnt < NTILES) {
                loadChunk(nnt, nkc, buf ^ 1);
                asm volatile("cp.async.wait_group 1;");
            } else {
                asm volatile("cp.async.wait_group 0;");
            }
            __syncthreads();

            const __half* B0 = Bb + buf * 128 * 136;
            #pragma unroll
            for (int ks = 0; ks < 8; ++ks) {
                int k0 = ks * 16;
                int ka = kc * 128 + k0;
                unsigned a[4][4];
                #pragma unroll
                for (int mi = 0; mi < 4; ++mi)
                    ldsm_x4(a[mi], Ah + (wm + mi * 16) * 264 + ka + aoff);
                #pragma unroll
                for (int jp = 0; jp < 2; ++jp) {
                    unsigned bf[4];
                    ldsm_x4(bf, B0 + (wn + jp * 16) * 136 + k0 + boff);
                    #pragma unroll
                    for (int mi = 0; mi < 4; ++mi) {
                        mma16816(c[mi][2 * jp],     a[mi], bf[0], bf[2]);
                        mma16816(c[mi][2 * jp + 1], a[mi], bf[1], bf[3]);
                    }
                }
            }
            buf ^= 1;
        }

        int n0 = nt * 128;
        #pragma unroll
        for (int mi = 0; mi < 4; ++mi) {
            int row = m0 + wm + mi * 16 + r;
            #pragma unroll
            for (int j = 0; j < 4; ++j) {
                int col = n0 + wn + j * 8 + q;
                if (col < V_) {
                    float2 bv = *(const float2*)(fcb + col);
                    *(float2*)(out + (size_t)row * V_ + col) =
                        make_float2(c[mi][j][0] + bv.x, c[mi][j][1] + bv.y);
                    *(float2*)(out + (size_t)(row + 8) * V_ + col) =
                        make_float2(c[mi][j][2] + bv.x, c[mi][j][3] + bv.y);
                }
            }
        }
    }
}

// ---------------- launch (single stream; overlap via fused heterogeneous grids) ----------------
extern "C" void kernel_launch(void* const* d_in, const int* in_sizes, int n_in,
                              void* d_out, int out_size) {
    const int*   seq   = (const int*)d_in[0];
    const int*   tlen  = (const int*)d_in[1];
    const float* emb   = (const float*)d_in[2];
    const float* kg    = (const float*)d_in[3];
    const float* Wih   = (const float*)d_in[4];
    const float* Whh   = (const float*)d_in[5];
    const float* bih   = (const float*)d_in[6];
    const float* bhh   = (const float*)d_in[7];
    const float* mlphW = (const float*)d_in[8];
    const float* mlphb = (const float*)d_in[9];
    const float* mlpW  = (const float*)d_in[10];
    const float* mlpb  = (const float*)d_in[11];
    const float* fcW   = (const float*)d_in[12];
    const float* fcb   = (const float*)d_in[13];
    float* out = (float*)d_out;

    cudaFuncSetAttribute(k_gx,  cudaFuncAttributeMaxDynamicSharedMemorySize, GX_SMEM);
    cudaFuncSetAttribute(k_gru, cudaFuncAttributeMaxDynamicSharedMemorySize, GRU_SMEM);
    cudaFuncSetAttribute(k_fc,  cudaFuncAttributeMaxDynamicSharedMemorySize, FC_SMEM);

    k_cvt_small<<<48, 256>>>(Wih, Whh, mlpW);
    k_gx<<<dim3(400, 4), 512, GX_SMEM>>>(seq, emb, bih, kg, fcW);  // gx + kgstat + cvt_fc
    k_kgfin<<<1, 64>>>();
    k_gru<<<GRU_GRID, 256, GRU_SMEM>>>(tlen, bhh, seq, kg, mlphW, mlphb);  // gru + bkg
    k_mlp<<<64, 256>>>(mlpb);
    k_fc<<<dim3(37, 4), 512, FC_SMEM>>>(fcb, out);
}